// round 11
// baseline (speedup 1.0000x reference)
#include <cuda_runtime.h>
#include <math.h>

#define H_IMG 1024
#define W_IMG 1280
#define NPIX  (H_IMG * W_IMG)
#define DAMPING 1e-6
// Exact float-level equivalent of  __fsqrt_rn(d2) > 0.2f
#define DIST_THR2_EQ 0.040000002831220626f
#define NORM_THR_F 0.93969262078590838405f  /* cos(20 deg) */

#define NBLOCKS 296      // 2 CTAs/SM co-resident on 148- and 152-SM parts
#define NTHREADS 256
#define NGROUPS (NPIX / 4)            // 327680 groups of 4 pixels
#define GROUPS_PER_TILE NTHREADS      // one group per thread per steal
#define NTILES (NGROUPS / GROUPS_PER_TILE)   // 1280
#define MAX_ITER 3

// Persistent state + scratch (no runtime allocation). Statics zero-init; the
// final solver restores counters to zero so graph replays are deterministic.
__device__ double g_poseD[16];
__device__ float  g_poseF[12];
__device__ double g_part[NBLOCKS * 28];   // per-CTA partials (plain stores)
__device__ unsigned int g_arrive;
__device__ volatile unsigned int g_phase;
__device__ unsigned int g_work[MAX_ITER];
__device__ float4 g_pk4[NPIX];   // (v1x, v1y, v1z, n1x)
__device__ float2 g_pk2[NPIX];   // (n1y, n1z)

// ---------------------------------------------------------------------------
// Two correctly-rounded divisions sharing ONE MUFU.RCP (== __fdiv_rn here).
__device__ __forceinline__ float2 div2_rn(float px, float py, float pz) {
    float y;
    asm("rcp.approx.f32 %0, %1;" : "=f"(y) : "f"(pz));
    float e  = __fmaf_rn(-pz, y, 1.0f);
    y = __fmaf_rn(y, e, y);
    float e2 = __fmaf_rn(-pz, y, 1.0f);
    y = __fmaf_rn(y, e2, y);
    float qu = __fmul_rn(px, y);
    float ru = __fmaf_rn(-pz, qu, px);
    qu = __fmaf_rn(ru, y, qu);
    float qv = __fmul_rn(py, y);
    float rv = __fmaf_rn(-pz, qv, py);
    qv = __fmaf_rn(rv, y, qv);
    return make_float2(qu, qv);
}

// ---------------------------------------------------------------------------
// fp64 solve on one thread, reading the 28 reduced sums from shared memory.
__device__ void solve_update(const double* acc, int write_out,
                             float* out, int out_size)
{
    double A[6][6], b[6];
    {
        int k = 0;
        for (int i = 0; i < 6; i++)
            for (int j = i; j < 6; j++) { A[i][j] = acc[k]; A[j][i] = acc[k]; k++; }
        double tr = 0.0;
        for (int i = 0; i < 6; i++) tr += A[i][i];
        for (int i = 0; i < 6; i++) A[i][i] += tr * DAMPING;
        for (int i = 0; i < 6; i++) b[i] = acc[21 + i];
    }
    const double count = acc[27];

    // LDLT
    double L[6][6], D[6];
    for (int j = 0; j < 6; j++) {
        double dj = A[j][j];
        for (int k = 0; k < j; k++) dj -= L[j][k] * L[j][k] * D[k];
        D[j] = dj;
        L[j][j] = 1.0;
        const double inv = 1.0 / dj;
        for (int i = j + 1; i < 6; i++) {
            double v = A[i][j];
            for (int k = 0; k < j; k++) v -= L[i][k] * L[j][k] * D[k];
            L[i][j] = v * inv;
        }
    }
    double y[6];
    for (int i = 0; i < 6; i++) {
        double v = b[i];
        for (int k = 0; k < i; k++) v -= L[i][k] * y[k];
        y[i] = v;
    }
    double xi[6];
    for (int i = 5; i >= 0; i--) {
        double v = y[i] / D[i];
        for (int k = i + 1; k < 6; k++) v -= L[k][i] * xi[k];
        xi[i] = v;
    }
    for (int i = 0; i < 6; i++) xi[i] = -xi[i];

    // exp_se3 via even Taylor series in theta^2 (exact to ~1e-15, t2 < 0.25)
    const double w0 = xi[0], w1 = xi[1], w2 = xi[2];
    const double vx = xi[3], vy = xi[4], vz = xi[5];
    const double t2 = w0 * w0 + w1 * w1 + w2 * w2;
    double E[3][3], Jm[3][3];
    if (t2 <= 1e-16) {
        for (int i = 0; i < 3; i++)
            for (int j = 0; j < 3; j++) {
                E[i][j]  = (i == j) ? 1.0 : 0.0;
                Jm[i][j] = (i == j) ? 1.0 : 0.0;
            }
    } else {
        double cA, cB, cC;
        if (t2 < 0.25) {
            cA = 1.0 + t2 * (-1.0 / 6.0 + t2 * (1.0 / 120.0 + t2 * (-1.0 / 5040.0 +
                 t2 * (1.0 / 362880.0 + t2 * (-1.0 / 39916800.0)))));
            cB = 0.5 + t2 * (-1.0 / 24.0 + t2 * (1.0 / 720.0 + t2 * (-1.0 / 40320.0 +
                 t2 * (1.0 / 3628800.0 + t2 * (-1.0 / 479001600.0)))));
            cC = 1.0 / 6.0 + t2 * (-1.0 / 120.0 + t2 * (1.0 / 5040.0 + t2 * (-1.0 / 362880.0 +
                 t2 * (1.0 / 39916800.0 + t2 * (-1.0 / 6227020800.0)))));
        } else {
            const double th = sqrt(t2);
            const double st = sin(th), ct = cos(th);
            cA = st / th;
            cB = (1.0 - ct) / t2;
            cC = (th - st) / (t2 * th);
        }
        const double wh[3][3] = { {0.0, -w2,  w1}, { w2, 0.0, -w0}, {-w1,  w0, 0.0} };
        double wh2[3][3];
        for (int i = 0; i < 3; i++)
            for (int j = 0; j < 3; j++) {
                double acc2 = 0.0;
                for (int k = 0; k < 3; k++) acc2 += wh[i][k] * wh[k][j];
                wh2[i][j] = acc2;
            }
        for (int i = 0; i < 3; i++)
            for (int j = 0; j < 3; j++) {
                const double eye = (i == j) ? 1.0 : 0.0;
                E[i][j]  = eye + cA * wh[i][j] + cB * wh2[i][j];
                Jm[i][j] = eye + cB * wh[i][j] + cC * wh2[i][j];
            }
    }
    double T[16];
    for (int i = 0; i < 3; i++) {
        for (int j = 0; j < 3; j++) T[i * 4 + j] = E[i][j];
        T[i * 4 + 3] = Jm[i][0] * vx + Jm[i][1] * vy + Jm[i][2] * vz;
    }
    T[12] = 0.0; T[13] = 0.0; T[14] = 0.0; T[15] = 1.0;

    double P[16];
    for (int i = 0; i < 4; i++)
        for (int j = 0; j < 4; j++) {
            double a2 = 0.0;
            for (int k = 0; k < 4; k++) a2 += T[i * 4 + k] * g_poseD[k * 4 + j];
            P[i * 4 + j] = a2;
        }
    for (int i = 0; i < 16; i++) g_poseD[i] = P[i];
    for (int r = 0; r < 3; r++) {
        for (int c = 0; c < 3; c++) g_poseF[r * 3 + c] = (float)P[r * 4 + c];
        g_poseF[9 + r] = (float)P[r * 4 + 3];
    }

    if (write_out) {
        for (int i = 0; i < 16 && i < out_size; i++) out[i] = (float)P[i];
        if (out_size >= 17) out[16] = (float)(count / (double)NPIX);
    }
}

// ---------------------------------------------------------------------------
// Single persistent kernel: pose init + pack + 3 ICP iterations + cleanup.
__global__ __launch_bounds__(NTHREADS, 2)
void icp_persistent(const float* __restrict__ pose10,
                    const float* __restrict__ v0d, const float* __restrict__ v1d,
                    const float* __restrict__ n0d, const float* __restrict__ n1d,
                    const float* __restrict__ Km,
                    float* __restrict__ out, int out_size)
{
    const float fx = Km[0], cx = Km[2], fy = Km[4], cy = Km[5];
    const int tglob = blockIdx.x * NTHREADS + threadIdx.x;
    const int ntot  = NBLOCKS * NTHREADS;

    __shared__ double sh[28];
    __shared__ unsigned int s_last;
    __shared__ int s_tile;

    // ---- Pose init (global thread 0) + pack phase, fused ----
    if (tglob == 0) {
        #pragma unroll
        for (int i = 0; i < 16; i++) g_poseD[i] = (double)pose10[i];
        #pragma unroll
        for (int r = 0; r < 3; r++) {
            #pragma unroll
            for (int c = 0; c < 3; c++) g_poseF[r * 3 + c] = pose10[r * 4 + c];
            g_poseF[9 + r] = pose10[r * 4 + 3];
        }
    }
    for (int t = tglob; t < NGROUPS; t += ntot) {
        const float4* v1q = (const float4*)(v1d) + 3 * t;
        const float4* n1q = (const float4*)(n1d) + 3 * t;
        const float4 a0 = v1q[0], a1 = v1q[1], a2 = v1q[2];
        const float4 b0 = n1q[0], b1 = n1q[1], b2 = n1q[2];
        const int p = 4 * t;
        g_pk4[p + 0] = make_float4(a0.x, a0.y, a0.z, b0.x);
        g_pk4[p + 1] = make_float4(a0.w, a1.x, a1.y, b0.w);
        g_pk4[p + 2] = make_float4(a1.z, a1.w, a2.x, b1.z);
        g_pk4[p + 3] = make_float4(a2.y, a2.z, a2.w, b2.y);
        g_pk2[p + 0] = make_float2(b0.y, b0.z);
        g_pk2[p + 1] = make_float2(b1.x, b1.y);
        g_pk2[p + 2] = make_float2(b1.w, b2.x);
        g_pk2[p + 3] = make_float2(b2.z, b2.w);
    }
    // grid barrier after pack+init (phase 1)
    if (threadIdx.x == 0) {
        __threadfence();
        s_last = atomicAdd(&g_arrive, 1u);
    }
    __syncthreads();
    if (s_last == (unsigned)(gridDim.x - 1) && threadIdx.x == 0) {
        __threadfence();
        g_phase = 1;
    }
    if (threadIdx.x == 0) {
        while (g_phase < 1u) { __nanosleep(100); }
    }
    __syncthreads();
    __threadfence();

    // ---- ICP iterations ----
    for (int it = 0; it < MAX_ITER; ++it) {
        const float R00 = g_poseF[0], R01 = g_poseF[1], R02 = g_poseF[2];
        const float R10 = g_poseF[3], R11 = g_poseF[4], R12 = g_poseF[5];
        const float R20 = g_poseF[6], R21 = g_poseF[7], R22 = g_poseF[8];
        const float tx  = g_poseF[9], ty  = g_poseF[10], tz = g_poseF[11];

        float s[28];
        #pragma unroll
        for (int i = 0; i < 28; i++) s[i] = 0.f;

        // work-stealing over tiles of 256 groups (1 group per thread per steal)
        for (;;) {
            __syncthreads();
            if (threadIdx.x == 0)
                s_tile = (int)atomicAdd(&g_work[it], 1u);
            __syncthreads();
            const int tile = s_tile;
            if (tile >= NTILES) break;
            const int t = tile * GROUPS_PER_TILE + threadIdx.x;

            const float4* v0q = (const float4*)(v0d) + 3 * t;
            const float4* n0q = (const float4*)(n0d) + 3 * t;
            const float4 a0 = v0q[0], a1 = v0q[1], a2 = v0q[2];
            const float4 b0 = n0q[0], b1 = n0q[1], b2 = n0q[2];

            const float X[4]  = {a0.x, a0.w, a1.z, a2.y};
            const float Y[4]  = {a0.y, a1.x, a1.w, a2.z};
            const float Z[4]  = {a0.z, a1.y, a2.x, a2.w};
            const float NXv[4] = {b0.x, b0.w, b1.z, b2.y};
            const float NYv[4] = {b0.y, b1.x, b1.w, b2.z};
            const float NZv[4] = {b0.z, b1.y, b2.x, b2.w};

            float PX[4], PY[4], PZ[4], QX[4], QY[4], QZ[4];
            int   G[4];
            bool  INV[4];
            #pragma unroll
            for (int i = 0; i < 4; i++) {
                const float x = X[i], y = Y[i], z = Z[i];
                PX[i] = __fmaf_rn(x, R00, __fmaf_rn(y, R01, __fmaf_rn(z, R02, tx)));
                PY[i] = __fmaf_rn(x, R10, __fmaf_rn(y, R11, __fmaf_rn(z, R12, ty)));
                PZ[i] = __fmaf_rn(x, R20, __fmaf_rn(y, R21, __fmaf_rn(z, R22, tz)));
                QX[i] = __fmaf_rn(NXv[i], R00, __fmaf_rn(NYv[i], R01, __fmul_rn(NZv[i], R02)));
                QY[i] = __fmaf_rn(NXv[i], R10, __fmaf_rn(NYv[i], R11, __fmul_rn(NZv[i], R12)));
                QZ[i] = __fmaf_rn(NXv[i], R20, __fmaf_rn(NYv[i], R21, __fmul_rn(NZv[i], R22)));
                const float2 q2 = div2_rn(PX[i], PY[i], PZ[i]);
                const float u = __fadd_rn(__fmul_rn(q2.x, fx), cx);
                const float v = __fadd_rn(__fmul_rn(q2.y, fy), cy);
                INV[i] = (u > 0.f) && (u < (float)(W_IMG - 1)) &&
                         (v > 0.f) && (v < (float)(H_IMG - 1));
                const float uif = fminf(fmaxf(rintf(u), 0.f), (float)(W_IMG - 1));
                const float vif = fminf(fmaxf(rintf(v), 0.f), (float)(H_IMG - 1));
                G[i] = (int)vif * W_IMG + (int)uif;
            }

            float4 PK4[4]; float2 PK2[4];
            #pragma unroll
            for (int i = 0; i < 4; i++) {
                PK4[i] = g_pk4[G[i]];
                PK2[i] = g_pk2[G[i]];
            }

            #pragma unroll
            for (int i = 0; i < 4; i++) {
                const float px = PX[i], py = PY[i], pz = PZ[i];
                const float ax = PK4[i].x, ay = PK4[i].y, az = PK4[i].z;
                const float bx = PK4[i].w, by = PK2[i].x, bz = PK2[i].y;
                const float dx = __fadd_rn(px, -ax);
                const float dy = __fadd_rn(py, -ay);
                const float dz = __fadd_rn(pz, -az);
                const float d2 = __fmaf_rn(dx, dx, __fmaf_rn(dy, dy, __fmul_rn(dz, dz)));
                const float ndot = __fmaf_rn(QX[i], bx, __fmaf_rn(QY[i], by, __fmul_rn(QZ[i], bz)));

                const bool valid = INV[i] && !(d2 > DIST_THR2_EQ) &&
                                   (Z[i] > 0.f) && (az > 0.f) && (ndot > NORM_THR_F);

                float r = __fmaf_rn(bx, dx, __fmaf_rn(by, dy, __fmul_rn(bz, dz)));
                float J[6];
                J[0] = __fadd_rn(__fmul_rn(py, bz), -__fmul_rn(pz, by));
                J[1] = __fadd_rn(__fmul_rn(pz, bx), -__fmul_rn(px, bz));
                J[2] = __fadd_rn(__fmul_rn(px, by), -__fmul_rn(py, bx));
                J[3] = bx; J[4] = by; J[5] = bz;
                if (!valid) {
                    r = 0.f;
                    #pragma unroll
                    for (int q = 0; q < 6; q++) J[q] = 0.f;
                }
                int kk = 0;
                #pragma unroll
                for (int a = 0; a < 6; a++)
                    #pragma unroll
                    for (int c = a; c < 6; c++) { s[kk] = __fmaf_rn(J[a], J[c], s[kk]); kk++; }
                #pragma unroll
                for (int a = 0; a < 6; a++) s[21 + a] = __fmaf_rn(J[a], r, s[21 + a]);
                if (valid) s[27] += 1.f;
            }
        }

        // warp reduction -> block partial in sh -> plain store to g_part
        #pragma unroll
        for (int i = 0; i < 28; i++) {
            #pragma unroll
            for (int o = 16; o > 0; o >>= 1)
                s[i] += __shfl_down_sync(0xffffffffu, s[i], o);
        }
        if (threadIdx.x < 28) sh[threadIdx.x] = 0.0;
        __syncthreads();
        if ((threadIdx.x & 31) == 0) {
            #pragma unroll
            for (int i = 0; i < 28; i++) atomicAdd(&sh[i], (double)s[i]);
        }
        __syncthreads();
        if (threadIdx.x < 28)
            g_part[blockIdx.x * 28 + threadIdx.x] = sh[threadIdx.x];
        __syncthreads();

        // ---- grid barrier; last-arriving CTA reduces partials + solves ----
        if (threadIdx.x == 0) {
            __threadfence();
            s_last = atomicAdd(&g_arrive, 1u);
        }
        __syncthreads();
        const bool solver_cta = (s_last == (unsigned)(gridDim.x * (it + 2) - 1));
        if (solver_cta) {
            if (threadIdx.x < 28) {
                double acc = 0.0;
                for (int c = 0; c < NBLOCKS; c++)
                    acc += g_part[c * 28 + threadIdx.x];
                sh[threadIdx.x] = acc;
            }
            __syncthreads();
            if (threadIdx.x == 0) {
                solve_update(sh, it == MAX_ITER - 1 ? 1 : 0, out, out_size);
                if (it == MAX_ITER - 1) {
                    // restore counters for the next graph replay
                    #pragma unroll
                    for (int i = 0; i < MAX_ITER; i++) g_work[i] = 0;
                    g_arrive = 0;
                    __threadfence();
                    g_phase = 0;
                } else {
                    __threadfence();
                    g_phase = it + 2;   // release
                }
            }
        }
        if (it < MAX_ITER - 1) {
            if (threadIdx.x == 0) {
                while (g_phase < (unsigned)(it + 2)) { __nanosleep(100); }
            }
            __syncthreads();
            __threadfence();
        }
    }
}

// ---------------------------------------------------------------------------
extern "C" void kernel_launch(void* const* d_in, const int* in_sizes, int n_in,
                              void* d_out, int out_size)
{
    const float* pose10 = (const float*)d_in[0];
    const float* v0     = (const float*)d_in[1];
    const float* v1     = (const float*)d_in[2];
    const float* n0     = (const float*)d_in[3];
    const float* n1     = (const float*)d_in[4];
    const float* K      = (const float*)d_in[5];
    float* out = (float*)d_out;

    icp_persistent<<<NBLOCKS, NTHREADS>>>(pose10, v0, v1, n0, n1, K, out, out_size);
}

// round 12
// speedup vs baseline: 1.2097x; 1.2097x over previous
#include <cuda_runtime.h>
#include <math.h>

#define H_IMG 1024
#define W_IMG 1280
#define NPIX  (H_IMG * W_IMG)
#define DAMPING 1e-6
// Exact float-level equivalent of  __fsqrt_rn(d2) > 0.2f
#define DIST_THR2_EQ 0.040000002831220626f
#define NORM_THR_F 0.93969262078590838405f  /* cos(20 deg) */

#define NBLOCKS 296      // 2 CTAs/SM co-resident on 148-SM (and 152-SM) parts
#define NTHREADS 256
#define NGROUPS (NPIX / 4)            // 327680 groups of 4 pixels
#define MAX_ITER 3

// Persistent state + scratch (no runtime allocation). Statics zero-init; the
// final solver restores counters to zero so graph replays are deterministic.
__device__ double g_poseD[16];
__device__ float  g_poseF[12];
__device__ double g_part[NBLOCKS * 28];   // per-CTA partials (plain stores)
__device__ unsigned int g_arrive;
__device__ volatile unsigned int g_phase;
__device__ float4 g_pk4[NPIX];   // (v1x, v1y, v1z, n1x)
__device__ float2 g_pk2[NPIX];   // (n1y, n1z)

// ---------------------------------------------------------------------------
// Two correctly-rounded divisions sharing ONE MUFU.RCP (== __fdiv_rn here).
__device__ __forceinline__ float2 div2_rn(float px, float py, float pz) {
    float y;
    asm("rcp.approx.f32 %0, %1;" : "=f"(y) : "f"(pz));
    float e  = __fmaf_rn(-pz, y, 1.0f);
    y = __fmaf_rn(y, e, y);
    float e2 = __fmaf_rn(-pz, y, 1.0f);
    y = __fmaf_rn(y, e2, y);
    float qu = __fmul_rn(px, y);
    float ru = __fmaf_rn(-pz, qu, px);
    qu = __fmaf_rn(ru, y, qu);
    float qv = __fmul_rn(py, y);
    float rv = __fmaf_rn(-pz, qv, py);
    qv = __fmaf_rn(rv, y, qv);
    return make_float2(qu, qv);
}

// ---------------------------------------------------------------------------
// fp64 solve on one thread, reading 28 reduced sums from shared memory.
__device__ void solve_update(const double* acc, int write_out,
                             float* out, int out_size)
{
    double A[6][6], b[6];
    {
        int k = 0;
        for (int i = 0; i < 6; i++)
            for (int j = i; j < 6; j++) { A[i][j] = acc[k]; A[j][i] = acc[k]; k++; }
        double tr = 0.0;
        for (int i = 0; i < 6; i++) tr += A[i][i];
        for (int i = 0; i < 6; i++) A[i][i] += tr * DAMPING;
        for (int i = 0; i < 6; i++) b[i] = acc[21 + i];
    }
    const double count = acc[27];

    // LDLT
    double L[6][6], D[6];
    for (int j = 0; j < 6; j++) {
        double dj = A[j][j];
        for (int k = 0; k < j; k++) dj -= L[j][k] * L[j][k] * D[k];
        D[j] = dj;
        L[j][j] = 1.0;
        const double inv = 1.0 / dj;
        for (int i = j + 1; i < 6; i++) {
            double v = A[i][j];
            for (int k = 0; k < j; k++) v -= L[i][k] * L[j][k] * D[k];
            L[i][j] = v * inv;
        }
    }
    double y[6];
    for (int i = 0; i < 6; i++) {
        double v = b[i];
        for (int k = 0; k < i; k++) v -= L[i][k] * y[k];
        y[i] = v;
    }
    double xi[6];
    for (int i = 5; i >= 0; i--) {
        double v = y[i] / D[i];
        for (int k = i + 1; k < 6; k++) v -= L[k][i] * xi[k];
        xi[i] = v;
    }
    for (int i = 0; i < 6; i++) xi[i] = -xi[i];

    // exp_se3 via even Taylor series in theta^2 (exact to ~1e-15, t2 < 0.25)
    const double w0 = xi[0], w1 = xi[1], w2 = xi[2];
    const double vx = xi[3], vy = xi[4], vz = xi[5];
    const double t2 = w0 * w0 + w1 * w1 + w2 * w2;
    double E[3][3], Jm[3][3];
    if (t2 <= 1e-16) {
        for (int i = 0; i < 3; i++)
            for (int j = 0; j < 3; j++) {
                E[i][j]  = (i == j) ? 1.0 : 0.0;
                Jm[i][j] = (i == j) ? 1.0 : 0.0;
            }
    } else {
        double cA, cB, cC;
        if (t2 < 0.25) {
            cA = 1.0 + t2 * (-1.0 / 6.0 + t2 * (1.0 / 120.0 + t2 * (-1.0 / 5040.0 +
                 t2 * (1.0 / 362880.0 + t2 * (-1.0 / 39916800.0)))));
            cB = 0.5 + t2 * (-1.0 / 24.0 + t2 * (1.0 / 720.0 + t2 * (-1.0 / 40320.0 +
                 t2 * (1.0 / 3628800.0 + t2 * (-1.0 / 479001600.0)))));
            cC = 1.0 / 6.0 + t2 * (-1.0 / 120.0 + t2 * (1.0 / 5040.0 + t2 * (-1.0 / 362880.0 +
                 t2 * (1.0 / 39916800.0 + t2 * (-1.0 / 6227020800.0)))));
        } else {
            const double th = sqrt(t2);
            const double st = sin(th), ct = cos(th);
            cA = st / th;
            cB = (1.0 - ct) / t2;
            cC = (th - st) / (t2 * th);
        }
        const double wh[3][3] = { {0.0, -w2,  w1}, { w2, 0.0, -w0}, {-w1,  w0, 0.0} };
        double wh2[3][3];
        for (int i = 0; i < 3; i++)
            for (int j = 0; j < 3; j++) {
                double acc2 = 0.0;
                for (int k = 0; k < 3; k++) acc2 += wh[i][k] * wh[k][j];
                wh2[i][j] = acc2;
            }
        for (int i = 0; i < 3; i++)
            for (int j = 0; j < 3; j++) {
                const double eye = (i == j) ? 1.0 : 0.0;
                E[i][j]  = eye + cA * wh[i][j] + cB * wh2[i][j];
                Jm[i][j] = eye + cB * wh[i][j] + cC * wh2[i][j];
            }
    }
    double T[16];
    for (int i = 0; i < 3; i++) {
        for (int j = 0; j < 3; j++) T[i * 4 + j] = E[i][j];
        T[i * 4 + 3] = Jm[i][0] * vx + Jm[i][1] * vy + Jm[i][2] * vz;
    }
    T[12] = 0.0; T[13] = 0.0; T[14] = 0.0; T[15] = 1.0;

    double P[16];
    for (int i = 0; i < 4; i++)
        for (int j = 0; j < 4; j++) {
            double a2 = 0.0;
            for (int k = 0; k < 4; k++) a2 += T[i * 4 + k] * g_poseD[k * 4 + j];
            P[i * 4 + j] = a2;
        }
    for (int i = 0; i < 16; i++) g_poseD[i] = P[i];
    for (int r = 0; r < 3; r++) {
        for (int c = 0; c < 3; c++) g_poseF[r * 3 + c] = (float)P[r * 4 + c];
        g_poseF[9 + r] = (float)P[r * 4 + 3];
    }

    if (write_out) {
        for (int i = 0; i < 16 && i < out_size; i++) out[i] = (float)P[i];
        if (out_size >= 17) out[16] = (float)(count / (double)NPIX);
    }
}

// ---------------------------------------------------------------------------
// Single persistent kernel: pose init + pack + 3 ICP iterations (static
// partition, NO intra-loop CTA barriers) + self-resetting counters.
__global__ __launch_bounds__(NTHREADS, 2)
void icp_persistent(const float* __restrict__ pose10,
                    const float* __restrict__ v0d, const float* __restrict__ v1d,
                    const float* __restrict__ n0d, const float* __restrict__ n1d,
                    const float* __restrict__ Km,
                    float* __restrict__ out, int out_size)
{
    const float fx = Km[0], cx = Km[2], fy = Km[4], cy = Km[5];
    const int tglob = blockIdx.x * NTHREADS + threadIdx.x;
    const int ntot  = NBLOCKS * NTHREADS;

    __shared__ double sh[28];
    __shared__ unsigned int s_last;

    // ---- Pose init (global thread 0) + pack phase, fused ----
    if (tglob == 0) {
        #pragma unroll
        for (int i = 0; i < 16; i++) g_poseD[i] = (double)pose10[i];
        #pragma unroll
        for (int r = 0; r < 3; r++) {
            #pragma unroll
            for (int c = 0; c < 3; c++) g_poseF[r * 3 + c] = pose10[r * 4 + c];
            g_poseF[9 + r] = pose10[r * 4 + 3];
        }
    }
    for (int t = tglob; t < NGROUPS; t += ntot) {
        const float4* v1q = (const float4*)(v1d) + 3 * t;
        const float4* n1q = (const float4*)(n1d) + 3 * t;
        const float4 a0 = v1q[0], a1 = v1q[1], a2 = v1q[2];
        const float4 b0 = n1q[0], b1 = n1q[1], b2 = n1q[2];
        const int p = 4 * t;
        g_pk4[p + 0] = make_float4(a0.x, a0.y, a0.z, b0.x);
        g_pk4[p + 1] = make_float4(a0.w, a1.x, a1.y, b0.w);
        g_pk4[p + 2] = make_float4(a1.z, a1.w, a2.x, b1.z);
        g_pk4[p + 3] = make_float4(a2.y, a2.z, a2.w, b2.y);
        g_pk2[p + 0] = make_float2(b0.y, b0.z);
        g_pk2[p + 1] = make_float2(b1.x, b1.y);
        g_pk2[p + 2] = make_float2(b1.w, b2.x);
        g_pk2[p + 3] = make_float2(b2.z, b2.w);
    }
    // grid barrier after pack+init (phase 1)
    if (threadIdx.x == 0) {
        __threadfence();
        s_last = atomicAdd(&g_arrive, 1u);
    }
    __syncthreads();
    if (s_last == (unsigned)(gridDim.x - 1) && threadIdx.x == 0) {
        __threadfence();
        g_phase = 1;
    }
    if (threadIdx.x == 0) {
        while (g_phase < 1u) { __nanosleep(100); }
    }
    __syncthreads();
    __threadfence();

    // ---- ICP iterations ----
    for (int it = 0; it < MAX_ITER; ++it) {
        const float R00 = g_poseF[0], R01 = g_poseF[1], R02 = g_poseF[2];
        const float R10 = g_poseF[3], R11 = g_poseF[4], R12 = g_poseF[5];
        const float R20 = g_poseF[6], R21 = g_poseF[7], R22 = g_poseF[8];
        const float tx  = g_poseF[9], ty  = g_poseF[10], tz = g_poseF[11];

        float s[28];
        #pragma unroll
        for (int i = 0; i < 28; i++) s[i] = 0.f;

        // static grid-stride over 4-pixel groups (R10 hot loop, no barriers)
        for (int t = tglob; t < NGROUPS; t += ntot) {
            const float4* v0q = (const float4*)(v0d) + 3 * t;
            const float4* n0q = (const float4*)(n0d) + 3 * t;
            const float4 a0 = v0q[0], a1 = v0q[1], a2 = v0q[2];
            const float4 b0 = n0q[0], b1 = n0q[1], b2 = n0q[2];

            const float X[4]  = {a0.x, a0.w, a1.z, a2.y};
            const float Y[4]  = {a0.y, a1.x, a1.w, a2.z};
            const float Z[4]  = {a0.z, a1.y, a2.x, a2.w};
            const float NXv[4] = {b0.x, b0.w, b1.z, b2.y};
            const float NYv[4] = {b0.y, b1.x, b1.w, b2.z};
            const float NZv[4] = {b0.z, b1.y, b2.x, b2.w};

            float PX[4], PY[4], PZ[4], QX[4], QY[4], QZ[4];
            int   G[4];
            bool  INV[4];
            #pragma unroll
            for (int i = 0; i < 4; i++) {
                const float x = X[i], y = Y[i], z = Z[i];
                PX[i] = __fmaf_rn(x, R00, __fmaf_rn(y, R01, __fmaf_rn(z, R02, tx)));
                PY[i] = __fmaf_rn(x, R10, __fmaf_rn(y, R11, __fmaf_rn(z, R12, ty)));
                PZ[i] = __fmaf_rn(x, R20, __fmaf_rn(y, R21, __fmaf_rn(z, R22, tz)));
                QX[i] = __fmaf_rn(NXv[i], R00, __fmaf_rn(NYv[i], R01, __fmul_rn(NZv[i], R02)));
                QY[i] = __fmaf_rn(NXv[i], R10, __fmaf_rn(NYv[i], R11, __fmul_rn(NZv[i], R12)));
                QZ[i] = __fmaf_rn(NXv[i], R20, __fmaf_rn(NYv[i], R21, __fmul_rn(NZv[i], R22)));
                const float2 q2 = div2_rn(PX[i], PY[i], PZ[i]);
                const float u = __fadd_rn(__fmul_rn(q2.x, fx), cx);
                const float v = __fadd_rn(__fmul_rn(q2.y, fy), cy);
                INV[i] = (u > 0.f) && (u < (float)(W_IMG - 1)) &&
                         (v > 0.f) && (v < (float)(H_IMG - 1));
                const float uif = fminf(fmaxf(rintf(u), 0.f), (float)(W_IMG - 1));
                const float vif = fminf(fmaxf(rintf(v), 0.f), (float)(H_IMG - 1));
                G[i] = (int)vif * W_IMG + (int)uif;
            }

            float4 PK4[4]; float2 PK2[4];
            #pragma unroll
            for (int i = 0; i < 4; i++) {
                PK4[i] = g_pk4[G[i]];
                PK2[i] = g_pk2[G[i]];
            }

            #pragma unroll
            for (int i = 0; i < 4; i++) {
                const float px = PX[i], py = PY[i], pz = PZ[i];
                const float ax = PK4[i].x, ay = PK4[i].y, az = PK4[i].z;
                const float bx = PK4[i].w, by = PK2[i].x, bz = PK2[i].y;
                const float dx = __fadd_rn(px, -ax);
                const float dy = __fadd_rn(py, -ay);
                const float dz = __fadd_rn(pz, -az);
                const float d2 = __fmaf_rn(dx, dx, __fmaf_rn(dy, dy, __fmul_rn(dz, dz)));
                const float ndot = __fmaf_rn(QX[i], bx, __fmaf_rn(QY[i], by, __fmul_rn(QZ[i], bz)));

                const bool valid = INV[i] && !(d2 > DIST_THR2_EQ) &&
                                   (Z[i] > 0.f) && (az > 0.f) && (ndot > NORM_THR_F);

                float r = __fmaf_rn(bx, dx, __fmaf_rn(by, dy, __fmul_rn(bz, dz)));
                float J[6];
                J[0] = __fadd_rn(__fmul_rn(py, bz), -__fmul_rn(pz, by));
                J[1] = __fadd_rn(__fmul_rn(pz, bx), -__fmul_rn(px, bz));
                J[2] = __fadd_rn(__fmul_rn(px, by), -__fmul_rn(py, bx));
                J[3] = bx; J[4] = by; J[5] = bz;
                if (!valid) {
                    r = 0.f;
                    #pragma unroll
                    for (int q = 0; q < 6; q++) J[q] = 0.f;
                }
                int kk = 0;
                #pragma unroll
                for (int a = 0; a < 6; a++)
                    #pragma unroll
                    for (int c = a; c < 6; c++) { s[kk] = __fmaf_rn(J[a], J[c], s[kk]); kk++; }
                #pragma unroll
                for (int a = 0; a < 6; a++) s[21 + a] = __fmaf_rn(J[a], r, s[21 + a]);
                if (valid) s[27] += 1.f;
            }
        }

        // warp reduction -> block partial in sh -> plain store to g_part
        #pragma unroll
        for (int i = 0; i < 28; i++) {
            #pragma unroll
            for (int o = 16; o > 0; o >>= 1)
                s[i] += __shfl_down_sync(0xffffffffu, s[i], o);
        }
        if (threadIdx.x < 28) sh[threadIdx.x] = 0.0;
        __syncthreads();
        if ((threadIdx.x & 31) == 0) {
            #pragma unroll
            for (int i = 0; i < 28; i++) atomicAdd(&sh[i], (double)s[i]);
        }
        __syncthreads();
        if (threadIdx.x < 28)
            g_part[blockIdx.x * 28 + threadIdx.x] = sh[threadIdx.x];
        __syncthreads();

        // ---- grid barrier; last CTA does a PARALLEL partial-reduce + solve
        if (threadIdx.x == 0) {
            __threadfence();
            s_last = atomicAdd(&g_arrive, 1u);
        }
        __syncthreads();
        const bool solver_cta = (s_last == (unsigned)(gridDim.x * (it + 2) - 1));
        if (solver_cta) {
            // 8 threads per statistic, stride-8 over the 296 CTAs
            const int stat = threadIdx.x >> 3;      // 0..31 (use 0..27)
            const int part = threadIdx.x & 7;
            double acc = 0.0;
            if (stat < 28) {
                for (int c = part; c < NBLOCKS; c += 8)
                    acc += g_part[c * 28 + stat];
                // combine the 8 partials (lanes stat*8..stat*8+7 are in-warp)
                #pragma unroll
                for (int o = 4; o > 0; o >>= 1)
                    acc += __shfl_down_sync(0xffffffffu, acc, o, 8);
                if (part == 0) sh[stat] = acc;
            }
            __syncthreads();
            if (threadIdx.x == 0) {
                solve_update(sh, it == MAX_ITER - 1 ? 1 : 0, out, out_size);
                if (it == MAX_ITER - 1) {
                    g_arrive = 0;                 // restore for graph replay
                    __threadfence();
                    g_phase = 0;
                } else {
                    __threadfence();
                    g_phase = it + 2;             // release
                }
            }
        }
        if (it < MAX_ITER - 1) {
            if (threadIdx.x == 0) {
                while (g_phase < (unsigned)(it + 2)) { __nanosleep(100); }
            }
            __syncthreads();
            __threadfence();
        }
    }
}

// ---------------------------------------------------------------------------
extern "C" void kernel_launch(void* const* d_in, const int* in_sizes, int n_in,
                              void* d_out, int out_size)
{
    const float* pose10 = (const float*)d_in[0];
    const float* v0     = (const float*)d_in[1];
    const float* v1     = (const float*)d_in[2];
    const float* n0     = (const float*)d_in[3];
    const float* n1     = (const float*)d_in[4];
    const float* K      = (const float*)d_in[5];
    float* out = (float*)d_out;

    icp_persistent<<<NBLOCKS, NTHREADS>>>(pose10, v0, v1, n0, n1, K, out, out_size);
}

// round 14
// speedup vs baseline: 1.3520x; 1.1176x over previous
#include <cuda_runtime.h>
#include <math.h>

#define H_IMG 1024
#define W_IMG 1280
#define NPIX  (H_IMG * W_IMG)
#define DAMPING 1e-6
// Exact float-level equivalent of  __fsqrt_rn(d2) > 0.2f
#define DIST_THR2_EQ 0.040000002831220626f
#define NORM_THR_F 0.93969262078590838405f  /* cos(20 deg) */

#define NBLOCKS 288      // 2 CTAs/SM * 144: co-resident on 148/152-SM parts
#define NTHREADS 256
#define NGROUPS (NPIX / 4)            // 327680 groups of 4 pixels
#define MAX_ITER 3

// Persistent state + packed gather scratch (no runtime allocation).
// Statics zero-init; final solver restores counters => replay-deterministic.
__device__ double g_poseD[16];
__device__ float  g_poseF[12];
__device__ double g_accum[28];
__device__ unsigned int g_arrive;
__device__ volatile unsigned int g_phase;
__device__ float4 g_pk4[NPIX];   // (v1x, v1y, v1z, n1x)
__device__ float2 g_pk2[NPIX];   // (n1y, n1z)

// ---------------------------------------------------------------------------
// Two correctly-rounded divisions sharing ONE MUFU.RCP (== __fdiv_rn here).
__device__ __forceinline__ float2 div2_rn(float px, float py, float pz) {
    float y;
    asm("rcp.approx.f32 %0, %1;" : "=f"(y) : "f"(pz));
    float e  = __fmaf_rn(-pz, y, 1.0f);
    y = __fmaf_rn(y, e, y);
    float e2 = __fmaf_rn(-pz, y, 1.0f);
    y = __fmaf_rn(y, e2, y);
    float qu = __fmul_rn(px, y);
    float ru = __fmaf_rn(-pz, qu, px);
    qu = __fmaf_rn(ru, y, qu);
    float qv = __fmul_rn(py, y);
    float rv = __fmaf_rn(-pz, qv, py);
    qv = __fmaf_rn(rv, y, qv);
    return make_float2(qu, qv);
}

// ---------------------------------------------------------------------------
// fp64 solve on one thread: LDLT 6x6, se3 exp via Taylor-in-theta^2.
__device__ void solve_update(int write_out, float* out, int out_size)
{
    double A[6][6], b[6];
    {
        int k = 0;
        for (int i = 0; i < 6; i++)
            for (int j = i; j < 6; j++) { A[i][j] = g_accum[k]; A[j][i] = g_accum[k]; k++; }
        double tr = 0.0;
        for (int i = 0; i < 6; i++) tr += A[i][i];
        for (int i = 0; i < 6; i++) A[i][i] += tr * DAMPING;
        for (int i = 0; i < 6; i++) b[i] = g_accum[21 + i];
    }
    const double count = g_accum[27];

    double L[6][6], D[6];
    for (int j = 0; j < 6; j++) {
        double dj = A[j][j];
        for (int k = 0; k < j; k++) dj -= L[j][k] * L[j][k] * D[k];
        D[j] = dj;
        L[j][j] = 1.0;
        const double inv = 1.0 / dj;
        for (int i = j + 1; i < 6; i++) {
            double v = A[i][j];
            for (int k = 0; k < j; k++) v -= L[i][k] * L[j][k] * D[k];
            L[i][j] = v * inv;
        }
    }
    double y[6];
    for (int i = 0; i < 6; i++) {
        double v = b[i];
        for (int k = 0; k < i; k++) v -= L[i][k] * y[k];
        y[i] = v;
    }
    double xi[6];
    for (int i = 5; i >= 0; i--) {
        double v = y[i] / D[i];
        for (int k = i + 1; k < 6; k++) v -= L[k][i] * xi[k];
        xi[i] = v;
    }
    for (int i = 0; i < 6; i++) xi[i] = -xi[i];

    const double w0 = xi[0], w1 = xi[1], w2 = xi[2];
    const double vx = xi[3], vy = xi[4], vz = xi[5];
    const double t2 = w0 * w0 + w1 * w1 + w2 * w2;
    double E[3][3], Jm[3][3];
    if (t2 <= 1e-16) {
        for (int i = 0; i < 3; i++)
            for (int j = 0; j < 3; j++) {
                E[i][j]  = (i == j) ? 1.0 : 0.0;
                Jm[i][j] = (i == j) ? 1.0 : 0.0;
            }
    } else {
        double cA, cB, cC;
        if (t2 < 0.25) {
            cA = 1.0 + t2 * (-1.0 / 6.0 + t2 * (1.0 / 120.0 + t2 * (-1.0 / 5040.0 +
                 t2 * (1.0 / 362880.0 + t2 * (-1.0 / 39916800.0)))));
            cB = 0.5 + t2 * (-1.0 / 24.0 + t2 * (1.0 / 720.0 + t2 * (-1.0 / 40320.0 +
                 t2 * (1.0 / 3628800.0 + t2 * (-1.0 / 479001600.0)))));
            cC = 1.0 / 6.0 + t2 * (-1.0 / 120.0 + t2 * (1.0 / 5040.0 + t2 * (-1.0 / 362880.0 +
                 t2 * (1.0 / 39916800.0 + t2 * (-1.0 / 6227020800.0)))));
        } else {
            const double th = sqrt(t2);
            const double st = sin(th), ct = cos(th);
            cA = st / th;
            cB = (1.0 - ct) / t2;
            cC = (th - st) / (t2 * th);
        }
        const double wh[3][3] = { {0.0, -w2,  w1}, { w2, 0.0, -w0}, {-w1,  w0, 0.0} };
        double wh2[3][3];
        for (int i = 0; i < 3; i++)
            for (int j = 0; j < 3; j++) {
                double acc2 = 0.0;
                for (int k = 0; k < 3; k++) acc2 += wh[i][k] * wh[k][j];
                wh2[i][j] = acc2;
            }
        for (int i = 0; i < 3; i++)
            for (int j = 0; j < 3; j++) {
                const double eye = (i == j) ? 1.0 : 0.0;
                E[i][j]  = eye + cA * wh[i][j] + cB * wh2[i][j];
                Jm[i][j] = eye + cB * wh[i][j] + cC * wh2[i][j];
            }
    }
    double T[16];
    for (int i = 0; i < 3; i++) {
        for (int j = 0; j < 3; j++) T[i * 4 + j] = E[i][j];
        T[i * 4 + 3] = Jm[i][0] * vx + Jm[i][1] * vy + Jm[i][2] * vz;
    }
    T[12] = 0.0; T[13] = 0.0; T[14] = 0.0; T[15] = 1.0;

    double P[16];
    for (int i = 0; i < 4; i++)
        for (int j = 0; j < 4; j++) {
            double a2 = 0.0;
            for (int k = 0; k < 4; k++) a2 += T[i * 4 + k] * g_poseD[k * 4 + j];
            P[i * 4 + j] = a2;
        }
    for (int i = 0; i < 16; i++) g_poseD[i] = P[i];
    for (int r = 0; r < 3; r++) {
        for (int c = 0; c < 3; c++) g_poseF[r * 3 + c] = (float)P[r * 4 + c];
        g_poseF[9 + r] = (float)P[r * 4 + 3];
    }

    if (write_out) {
        for (int i = 0; i < 16 && i < out_size; i++) out[i] = (float)P[i];
        if (out_size >= 17) out[16] = (float)(count / (double)NPIX);
    }
    for (int i = 0; i < 28; i++) g_accum[i] = 0.0;
}

// ---------------------------------------------------------------------------
// Persistent kernel: fused pose init + pack + 3 ICP iterations (R10 hot loop
// and R10 reduction tail, verbatim).
__global__ __launch_bounds__(NTHREADS, 2)
void icp_persistent(const float* __restrict__ pose10,
                    const float* __restrict__ v0d, const float* __restrict__ v1d,
                    const float* __restrict__ n0d, const float* __restrict__ n1d,
                    const float* __restrict__ Km,
                    float* __restrict__ out, int out_size)
{
    const float fx = Km[0], cx = Km[2], fy = Km[4], cy = Km[5];
    const int tglob = blockIdx.x * NTHREADS + threadIdx.x;
    const int ntot  = NBLOCKS * NTHREADS;

    __shared__ double sh[28];
    __shared__ unsigned int s_last;

    // ---- Pose init (global thread 0) + pack phase, fused ----
    if (tglob == 0) {
        #pragma unroll
        for (int i = 0; i < 16; i++) g_poseD[i] = (double)pose10[i];
        #pragma unroll
        for (int r = 0; r < 3; r++) {
            #pragma unroll
            for (int c = 0; c < 3; c++) g_poseF[r * 3 + c] = pose10[r * 4 + c];
            g_poseF[9 + r] = pose10[r * 4 + 3];
        }
    }
    for (int t = tglob; t < NGROUPS; t += ntot) {
        const float4* v1q = (const float4*)(v1d) + 3 * t;
        const float4* n1q = (const float4*)(n1d) + 3 * t;
        const float4 a0 = v1q[0], a1 = v1q[1], a2 = v1q[2];
        const float4 b0 = n1q[0], b1 = n1q[1], b2 = n1q[2];
        const int p = 4 * t;
        g_pk4[p + 0] = make_float4(a0.x, a0.y, a0.z, b0.x);
        g_pk4[p + 1] = make_float4(a0.w, a1.x, a1.y, b0.w);
        g_pk4[p + 2] = make_float4(a1.z, a1.w, a2.x, b1.z);
        g_pk4[p + 3] = make_float4(a2.y, a2.z, a2.w, b2.y);
        g_pk2[p + 0] = make_float2(b0.y, b0.z);
        g_pk2[p + 1] = make_float2(b1.x, b1.y);
        g_pk2[p + 2] = make_float2(b1.w, b2.x);
        g_pk2[p + 3] = make_float2(b2.z, b2.w);
    }
    // grid barrier after pack+init (phase 1)
    if (threadIdx.x == 0) {
        __threadfence();
        s_last = atomicAdd(&g_arrive, 1u);
    }
    __syncthreads();
    if (s_last == (unsigned)(gridDim.x - 1) && threadIdx.x == 0) {
        __threadfence();
        g_phase = 1;
    }
    if (threadIdx.x == 0) {
        while (g_phase < 1u) { __nanosleep(100); }
    }
    __syncthreads();
    __threadfence();

    // ---- ICP iterations (R10 hot loop) ----
    for (int it = 0; it < MAX_ITER; ++it) {
        const float R00 = g_poseF[0], R01 = g_poseF[1], R02 = g_poseF[2];
        const float R10 = g_poseF[3], R11 = g_poseF[4], R12 = g_poseF[5];
        const float R20 = g_poseF[6], R21 = g_poseF[7], R22 = g_poseF[8];
        const float tx  = g_poseF[9], ty  = g_poseF[10], tz = g_poseF[11];

        float s[28];
        #pragma unroll
        for (int i = 0; i < 28; i++) s[i] = 0.f;

        for (int t = tglob; t < NGROUPS; t += ntot) {
            const float4* v0q = (const float4*)(v0d) + 3 * t;
            const float4* n0q = (const float4*)(n0d) + 3 * t;
            const float4 a0 = v0q[0], a1 = v0q[1], a2 = v0q[2];
            const float4 b0 = n0q[0], b1 = n0q[1], b2 = n0q[2];

            const float X[4]  = {a0.x, a0.w, a1.z, a2.y};
            const float Y[4]  = {a0.y, a1.x, a1.w, a2.z};
            const float Z[4]  = {a0.z, a1.y, a2.x, a2.w};
            const float NXv[4] = {b0.x, b0.w, b1.z, b2.y};
            const float NYv[4] = {b0.y, b1.x, b1.w, b2.z};
            const float NZv[4] = {b0.z, b1.y, b2.x, b2.w};

            float PX[4], PY[4], PZ[4], QX[4], QY[4], QZ[4];
            int   G[4];
            bool  INV[4];
            #pragma unroll
            for (int i = 0; i < 4; i++) {
                const float x = X[i], y = Y[i], z = Z[i];
                PX[i] = __fmaf_rn(x, R00, __fmaf_rn(y, R01, __fmaf_rn(z, R02, tx)));
                PY[i] = __fmaf_rn(x, R10, __fmaf_rn(y, R11, __fmaf_rn(z, R12, ty)));
                PZ[i] = __fmaf_rn(x, R20, __fmaf_rn(y, R21, __fmaf_rn(z, R22, tz)));
                QX[i] = __fmaf_rn(NXv[i], R00, __fmaf_rn(NYv[i], R01, __fmul_rn(NZv[i], R02)));
                QY[i] = __fmaf_rn(NXv[i], R10, __fmaf_rn(NYv[i], R11, __fmul_rn(NZv[i], R12)));
                QZ[i] = __fmaf_rn(NXv[i], R20, __fmaf_rn(NYv[i], R21, __fmul_rn(NZv[i], R22)));
                const float2 q2 = div2_rn(PX[i], PY[i], PZ[i]);
                const float u = __fadd_rn(__fmul_rn(q2.x, fx), cx);
                const float v = __fadd_rn(__fmul_rn(q2.y, fy), cy);
                INV[i] = (u > 0.f) && (u < (float)(W_IMG - 1)) &&
                         (v > 0.f) && (v < (float)(H_IMG - 1));
                const float uif = fminf(fmaxf(rintf(u), 0.f), (float)(W_IMG - 1));
                const float vif = fminf(fmaxf(rintf(v), 0.f), (float)(H_IMG - 1));
                G[i] = (int)vif * W_IMG + (int)uif;
            }

            float4 PK4[4]; float2 PK2[4];
            #pragma unroll
            for (int i = 0; i < 4; i++) {
                PK4[i] = g_pk4[G[i]];
                PK2[i] = g_pk2[G[i]];
            }

            #pragma unroll
            for (int i = 0; i < 4; i++) {
                const float px = PX[i], py = PY[i], pz = PZ[i];
                const float ax = PK4[i].x, ay = PK4[i].y, az = PK4[i].z;
                const float bx = PK4[i].w, by = PK2[i].x, bz = PK2[i].y;
                const float dx = __fadd_rn(px, -ax);
                const float dy = __fadd_rn(py, -ay);
                const float dz = __fadd_rn(pz, -az);
                const float d2 = __fmaf_rn(dx, dx, __fmaf_rn(dy, dy, __fmul_rn(dz, dz)));
                const float ndot = __fmaf_rn(QX[i], bx, __fmaf_rn(QY[i], by, __fmul_rn(QZ[i], bz)));

                const bool valid = INV[i] && !(d2 > DIST_THR2_EQ) &&
                                   (Z[i] > 0.f) && (az > 0.f) && (ndot > NORM_THR_F);

                float r = __fmaf_rn(bx, dx, __fmaf_rn(by, dy, __fmul_rn(bz, dz)));
                float J[6];
                J[0] = __fadd_rn(__fmul_rn(py, bz), -__fmul_rn(pz, by));
                J[1] = __fadd_rn(__fmul_rn(pz, bx), -__fmul_rn(px, bz));
                J[2] = __fadd_rn(__fmul_rn(px, by), -__fmul_rn(py, bx));
                J[3] = bx; J[4] = by; J[5] = bz;
                if (!valid) {
                    r = 0.f;
                    #pragma unroll
                    for (int q = 0; q < 6; q++) J[q] = 0.f;
                }
                int kk = 0;
                #pragma unroll
                for (int a = 0; a < 6; a++)
                    #pragma unroll
                    for (int c = a; c < 6; c++) { s[kk] = __fmaf_rn(J[a], J[c], s[kk]); kk++; }
                #pragma unroll
                for (int a = 0; a < 6; a++) s[21 + a] = __fmaf_rn(J[a], r, s[21 + a]);
                if (valid) s[27] += 1.f;
            }
        }

        // R10 reduction tail: warp shuffles -> shared doubles -> global atomics
        #pragma unroll
        for (int i = 0; i < 28; i++) {
            #pragma unroll
            for (int o = 16; o > 0; o >>= 1)
                s[i] += __shfl_down_sync(0xffffffffu, s[i], o);
        }
        if (threadIdx.x < 28) sh[threadIdx.x] = 0.0;
        __syncthreads();
        if ((threadIdx.x & 31) == 0) {
            #pragma unroll
            for (int i = 0; i < 28; i++) atomicAdd(&sh[i], (double)s[i]);
        }
        __syncthreads();
        if (threadIdx.x < 28) atomicAdd(&g_accum[threadIdx.x], sh[threadIdx.x]);

        // ---- grid barrier + inline solve by the last-arriving CTA ----
        if (threadIdx.x == 0) {
            __threadfence();
            s_last = atomicAdd(&g_arrive, 1u);
        }
        __syncthreads();
        const bool is_solver = (s_last == (unsigned)(gridDim.x * (it + 2) - 1));
        if (is_solver && threadIdx.x == 0) {
            solve_update(it == MAX_ITER - 1 ? 1 : 0, out, out_size);
            if (it == MAX_ITER - 1) {
                g_arrive = 0;                 // restore for graph replay
                __threadfence();
                g_phase = 0;
            } else {
                __threadfence();
                g_phase = it + 2;             // release
            }
        }
        if (it < MAX_ITER - 1) {
            if (threadIdx.x == 0) {
                while (g_phase < (unsigned)(it + 2)) { __nanosleep(100); }
            }
            __syncthreads();
            __threadfence();
        }
    }
}

// ---------------------------------------------------------------------------
extern "C" void kernel_launch(void* const* d_in, const int* in_sizes, int n_in,
                              void* d_out, int out_size)
{
    const float* pose10 = (const float*)d_in[0];
    const float* v0     = (const float*)d_in[1];
    const float* v1     = (const float*)d_in[2];
    const float* n0     = (const float*)d_in[3];
    const float* n1     = (const float*)d_in[4];
    const float* K      = (const float*)d_in[5];
    float* out = (float*)d_out;

    icp_persistent<<<NBLOCKS, NTHREADS>>>(pose10, v0, v1, n0, n1, K, out, out_size);
}